// round 1
// baseline (speedup 1.0000x reference)
#include <cuda_runtime.h>
#include <cstdint>
#include <math.h>

// Problem constants
#define BB   2
#define SS   2048
#define HID  2048
#define HH   8
#define KHH  1
#define DD   256
#define HDIM (HH*DD)      // 2048
#define KDIM (KHH*DD)     // 256
#define HALF (DD/2)       // 128

// Scratch (device globals only; no allocation allowed)
__device__ float g_q[(size_t)BB*SS*HH*DD];      // (B,S,H*D)
__device__ float g_k[(size_t)BB*SS*KHH*DD];     // (B,S,KH*D)
__device__ float g_v[(size_t)BB*SS*KHH*DD];
__device__ float g_ctx[(size_t)BB*SS*HH*DD];    // (B,S,H*D)
__device__ float g_attn_fallback[(size_t)BB*HH*SS*SS]; // used only if attn not in d_out

// ---------------------------------------------------------------------------
// Generic 64x64x32 fp32 tiled GEMM core.
//   C[m][n] = sum_k A[m][k] * (BT ? B[n][k] : B[k][n])  (+ bias[n] if bias)
// All dims assumed multiples of tile sizes (true for every call here).
// 256 threads, 4x4 register tile per thread.
// ---------------------------------------------------------------------------
template<bool BT>
__device__ __forceinline__ void gemm_tile(
    const float* __restrict__ A, int lda,
    const float* __restrict__ B, int ldb,
    float*       __restrict__ C, int ldc,
    int K, const float* __restrict__ bias,
    int m0, int n0)
{
    __shared__ float sA[64][32];   // sA[m][k]
    __shared__ float sB[32][64];   // sB[k][n]

    const int tid = threadIdx.x;
    const int tx  = tid & 15;      // 16 col groups
    const int ty  = tid >> 4;      // 16 row groups

    float acc[4][4];
#pragma unroll
    for (int i = 0; i < 4; i++)
#pragma unroll
        for (int j = 0; j < 4; j++) acc[i][j] = 0.0f;

    for (int k0 = 0; k0 < K; k0 += 32) {
        // ---- load A tile (64 rows x 32 k), float4 along k ----
#pragma unroll
        for (int r = 0; r < 2; r++) {
            int f   = tid + r * 256;       // 0..511 float4 slots
            int row = f >> 3;              // 0..63
            int kq  = f & 7;               // 0..7 (x4 floats)
            float4 va = *(const float4*)&A[(size_t)(m0 + row) * lda + k0 + kq * 4];
            *(float4*)&sA[row][kq * 4] = va;
        }
        // ---- load B tile ----
        if (BT) {
            // B is (N,K) row-major: load float4 along k, scatter into sB[k][n]
#pragma unroll
            for (int r = 0; r < 2; r++) {
                int f   = tid + r * 256;
                int row = f >> 3;          // n within tile
                int kq  = f & 7;
                float4 vb = *(const float4*)&B[(size_t)(n0 + row) * ldb + k0 + kq * 4];
                sB[kq * 4 + 0][row] = vb.x;
                sB[kq * 4 + 1][row] = vb.y;
                sB[kq * 4 + 2][row] = vb.z;
                sB[kq * 4 + 3][row] = vb.w;
            }
        } else {
            // B is (K,N) row-major: float4 along n, store contiguous
#pragma unroll
            for (int r = 0; r < 2; r++) {
                int f    = tid + r * 256;
                int krow = f >> 4;         // 0..31
                int nq   = f & 15;         // 0..15 (x4 floats)
                float4 vb = *(const float4*)&B[(size_t)(k0 + krow) * ldb + n0 + nq * 4];
                *(float4*)&sB[krow][nq * 4] = vb;
            }
        }
        __syncthreads();

#pragma unroll
        for (int k = 0; k < 32; k++) {
            float ra[4];
#pragma unroll
            for (int i = 0; i < 4; i++) ra[i] = sA[ty * 4 + i][k];
            float4 b4 = *(const float4*)&sB[k][tx * 4];
            float rb[4] = {b4.x, b4.y, b4.z, b4.w};
#pragma unroll
            for (int i = 0; i < 4; i++)
#pragma unroll
                for (int j = 0; j < 4; j++)
                    acc[i][j] += ra[i] * rb[j];
        }
        __syncthreads();
    }

#pragma unroll
    for (int i = 0; i < 4; i++) {
        int row = m0 + ty * 4 + i;
#pragma unroll
        for (int j = 0; j < 4; j++) {
            int col = n0 + tx * 4 + j;
            float v = acc[i][j];
            if (bias) v += bias[col];
            C[(size_t)row * ldc + col] = v;
        }
    }
}

// ---------------------------------------------------------------------------
// Stage 1: fused QKV projection.  hidden (4096,2048) x {Wq,Wk,Wv}^T (+bias)
// N space: [0,2048) -> q, [2048,2304) -> k, [2304,2560) -> v
// ---------------------------------------------------------------------------
__global__ __launch_bounds__(256)
void qkv_kernel(const float* __restrict__ hs,
                const float* __restrict__ Wq, const float* __restrict__ bq,
                const float* __restrict__ Wk, const float* __restrict__ bk,
                const float* __restrict__ Wv, const float* __restrict__ bv)
{
    int n0 = blockIdx.x * 64;
    int m0 = blockIdx.y * 64;
    const float* W; const float* bias; float* C; int ldc; int nloc;
    if (n0 < 2048)       { W = Wq; bias = bq; C = g_q; ldc = HDIM; nloc = n0; }
    else if (n0 < 2304)  { W = Wk; bias = bk; C = g_k; ldc = KDIM; nloc = n0 - 2048; }
    else                 { W = Wv; bias = bv; C = g_v; ldc = KDIM; nloc = n0 - 2304; }
    gemm_tile<true>(hs, HID, W, HID, C, ldc, HID, bias, m0, nloc);
}

// ---------------------------------------------------------------------------
// Stage 2: RoPE in place on g_q and g_k.
// ---------------------------------------------------------------------------
__global__ __launch_bounds__(256)
void rope_kernel(const int* __restrict__ pos_ids)
{
    const int QP = BB * SS * HH * HALF;   // q rotation pairs
    const int KP = BB * SS * KHH * HALF;  // k rotation pairs
    int idx = blockIdx.x * 256 + threadIdx.x;
    float* buf; int nh;
    if (idx < QP)            { buf = g_q; nh = HH; }
    else if (idx < QP + KP)  { idx -= QP; buf = g_k; nh = KHH; }
    else return;

    int j    = idx & (HALF - 1);
    int rest = idx >> 7;           // HALF = 128
    int h    = rest % nh; rest /= nh;
    int s    = rest % SS;
    int b    = rest / SS;

    size_t base = (((size_t)b * SS + s) * nh + h) * DD;
    int p = pos_ids[(size_t)b * SS + s];

    // phase computed in double (matches jax fp32 rope to ~1e-4 abs)
    double inv_freq = exp(-((double)(2 * j) / (double)DD) * 9.210340371976184); // ln(10000)
    float  fr = (float)((double)p * inv_freq);
    float  c, sn;
    __sincosf(fr, &sn, &c);
    // __sincosf is fast-math; use accurate version instead:
    sn = sinf(fr); c = cosf(fr);

    float x1 = buf[base + j];
    float x2 = buf[base + HALF + j];
    buf[base + j]        = c * x1 - sn * x2;
    buf[base + HALF + j] = sn * x1 + c * x2;
}

// ---------------------------------------------------------------------------
// Stage 3: scores = Q . K^T   (raw dot products; scale+mask folded into softmax)
// grid: (32, 32, 16)  z = b*H + h
// ---------------------------------------------------------------------------
__global__ __launch_bounds__(256)
void score_kernel(float* __restrict__ attn)
{
    int z = blockIdx.z; int b = z >> 3; int h = z & 7;
    const float* A  = g_q + ((size_t)b * SS * HH + h) * DD;  // row stride H*D
    const float* Bm = g_k + (size_t)b * SS * KDIM;           // (S, 256) row-major
    float* C = attn + (size_t)z * SS * SS;
    gemm_tile<true>(A, HDIM, Bm, KDIM, C, SS, DD, nullptr, blockIdx.y * 64, blockIdx.x * 64);
}

// ---------------------------------------------------------------------------
// Stage 4: softmax over each attn row (scale by D^-0.5 and add mask first).
// one block of 256 threads per row (2048 elems, 8/thread)
// ---------------------------------------------------------------------------
__global__ __launch_bounds__(256)
void softmax_kernel(float* __restrict__ attn, const float* __restrict__ mask)
{
    size_t r = blockIdx.x;                    // [0, B*H*S)
    int b = (int)(r / (HH * SS));
    float* row = attn + r * (size_t)SS;
    const float* mrow = mask + (size_t)b * SS;
    int t = threadIdx.x;

    float vals[8];
    float mx = -1e30f;
#pragma unroll
    for (int i = 0; i < 8; i++) {
        float v = row[t + i * 256] * 0.0625f + mrow[t + i * 256];
        vals[i] = v;
        mx = fmaxf(mx, v);
    }
    __shared__ float sred[256];
    sred[t] = mx; __syncthreads();
    for (int s = 128; s > 0; s >>= 1) {
        if (t < s) sred[t] = fmaxf(sred[t], sred[t + s]);
        __syncthreads();
    }
    mx = sred[0]; __syncthreads();

    float sum = 0.0f;
#pragma unroll
    for (int i = 0; i < 8; i++) { vals[i] = expf(vals[i] - mx); sum += vals[i]; }
    sred[t] = sum; __syncthreads();
    for (int s = 128; s > 0; s >>= 1) {
        if (t < s) sred[t] += sred[t + s];
        __syncthreads();
    }
    float inv = 1.0f / sred[0];
#pragma unroll
    for (int i = 0; i < 8; i++) row[t + i * 256] = vals[i] * inv;
}

// ---------------------------------------------------------------------------
// Stage 5: ctx = attn . V     grid: (4, 32, 16)
// ---------------------------------------------------------------------------
__global__ __launch_bounds__(256)
void av_kernel(const float* __restrict__ attn)
{
    int z = blockIdx.z; int b = z >> 3; int h = z & 7;
    const float* A = attn + (size_t)z * SS * SS;          // (S,S)
    const float* V = g_v  + (size_t)b * SS * KDIM;        // (S,256)
    float* C = g_ctx + (size_t)b * SS * HDIM + (size_t)h * DD;
    gemm_tile<false>(A, SS, V, KDIM, C, HDIM, SS, nullptr, blockIdx.y * 64, blockIdx.x * 64);
}

// ---------------------------------------------------------------------------
// Stage 6: out = ctx . Wo^T + bo     grid: (32, 64)
// ---------------------------------------------------------------------------
__global__ __launch_bounds__(256)
void out_kernel(const float* __restrict__ Wo, const float* __restrict__ bo,
                float* __restrict__ out)
{
    gemm_tile<true>(g_ctx, HDIM, Wo, HDIM, out, HID, HDIM, bo, blockIdx.y * 64, blockIdx.x * 64);
}

// ---------------------------------------------------------------------------
extern "C" void kernel_launch(void* const* d_in, const int* in_sizes, int n_in,
                              void* d_out, int out_size)
{
    const float* hs   = (const float*)d_in[0];
    const float* mask = (const float*)d_in[1];
    const int*   pos  = (const int*)  d_in[2];
    const float* Wq   = (const float*)d_in[3];
    const float* bq   = (const float*)d_in[4];
    const float* Wk   = (const float*)d_in[5];
    const float* bk   = (const float*)d_in[6];
    const float* Wv   = (const float*)d_in[7];
    const float* bv   = (const float*)d_in[8];
    const float* Wo   = (const float*)d_in[9];
    const float* bo   = (const float*)d_in[10];

    float* out = (float*)d_out;
    const size_t OUT_ELEMS  = (size_t)BB * SS * HID;          // 8,388,608
    const size_t ATTN_ELEMS = (size_t)BB * HH * SS * SS;      // 67,108,864

    float* attn;
    if ((size_t)out_size >= OUT_ELEMS + ATTN_ELEMS) {
        attn = out + OUT_ELEMS;                                // (out, attn) flattened
    } else {
        cudaGetSymbolAddress((void**)&attn, g_attn_fallback);  // attn not an output
    }

    // 1) QKV projection: N = 2048 + 256 + 256 = 2560
    qkv_kernel<<<dim3(2560 / 64, (BB * SS) / 64), 256>>>(hs, Wq, bq, Wk, bk, Wv, bv);

    // 2) RoPE on q and k
    {
        int total = BB * SS * HH * HALF + BB * SS * KHH * HALF;
        rope_kernel<<<(total + 255) / 256, 256>>>(pos);
    }

    // 3) scores
    score_kernel<<<dim3(SS / 64, SS / 64, BB * HH), 256>>>(attn);

    // 4) softmax (scale + mask folded in)
    softmax_kernel<<<BB * HH * SS, 256>>>(attn, mask);

    // 5) ctx = attn . V
    av_kernel<<<dim3(KDIM / 64, SS / 64, BB * HH), 256>>>(attn);

    // 6) out projection
    out_kernel<<<dim3(HID / 64, (BB * SS) / 64), 256>>>(Wo, bo, out);
}

// round 2
// speedup vs baseline: 3.1708x; 3.1708x over previous
#include <cuda_runtime.h>
#include <cstdint>
#include <math.h>

// Problem constants
#define BB   2
#define SS   2048
#define HID  2048
#define HH   8
#define KHH  1
#define DD   256
#define HDIM (HH*DD)      // 2048
#define KDIM (KHH*DD)     // 256
#define HALF (DD/2)       // 128

// Scratch (device globals only)
__device__ float g_q[(size_t)BB*SS*HH*DD];
__device__ float g_k[(size_t)BB*SS*KHH*DD];
__device__ float g_v[(size_t)BB*SS*KHH*DD];
__device__ float g_ctx[(size_t)BB*SS*HH*DD];
__device__ float g_attn_fallback[(size_t)BB*HH*SS*SS];

// ---------------------------------------------------------------------------
// helpers
// ---------------------------------------------------------------------------
__device__ __forceinline__ uint32_t f2tf32(float x) {
    uint32_t r;
    asm("cvt.rna.tf32.f32 %0, %1;" : "=r"(r) : "f"(x));
    return r;
}
__device__ __forceinline__ void cp16(void* dst, const void* src) {
    uint32_t d = (uint32_t)__cvta_generic_to_shared(dst);
    asm volatile("cp.async.cg.shared.global [%0], [%1], 16;" :: "r"(d), "l"(src));
}
__device__ __forceinline__ void cp_commit() { asm volatile("cp.async.commit_group;"); }
template<int N>
__device__ __forceinline__ void cp_wait() { asm volatile("cp.async.wait_group %0;" :: "n"(N)); }

__device__ __forceinline__ void mma_tf32(float acc[4], const uint32_t a[4], const uint32_t b[2]) {
    asm volatile(
        "mma.sync.aligned.m16n8k8.row.col.f32.tf32.tf32.f32 "
        "{%0,%1,%2,%3}, {%4,%5,%6,%7}, {%8,%9}, {%0,%1,%2,%3};\n"
        : "+f"(acc[0]), "+f"(acc[1]), "+f"(acc[2]), "+f"(acc[3])
        : "r"(a[0]), "r"(a[1]), "r"(a[2]), "r"(a[3]), "r"(b[0]), "r"(b[1]));
}

// ---------------------------------------------------------------------------
// tf32 tensor-core GEMM core: block tile 128x128, k-chunk 32, double-buffered
// cp.async. 256 threads = 8 warps in 2(m) x 4(n); each warp computes 64x32
// via 4x4 grid of m16n8k8 MMAs per 8-wide k-step.
//   C = A (MxK row-major, lda) * (BT ? B^T (B is NxK, ldb) : B (KxN, ldb))
// All dims multiples of tile sizes at every call site.
// ---------------------------------------------------------------------------
#define PA 36     // smem pitch for m/n-major tiles (bank-conflict free, 16B aligned)
#define PBN 136   // smem pitch for k-major (NN) B tile

template<bool BT>
__device__ __forceinline__ void mma_gemm(
    const float* __restrict__ A, int lda,
    const float* __restrict__ B, int ldb,
    float*       __restrict__ C, int ldc,
    int K, const float* __restrict__ bias,
    int m0, int n0)
{
    extern __shared__ float smem[];
    float* sA = smem;                 // [2][128][PA]
    float* sB = smem + 2 * 128 * PA;  // BT: [2][128][PA]   NN: [2][32][PBN]

    const int tid  = threadIdx.x;
    const int lane = tid & 31;
    const int wid  = tid >> 5;
    const int wm   = wid >> 2;        // 0..1  (64 rows each)
    const int wn   = wid & 3;         // 0..3  (32 cols each)
    const int lr   = lane >> 2;       // 0..7
    const int lc   = lane & 3;        // 0..3

    float acc[4][4][4];
#pragma unroll
    for (int i = 0; i < 4; i++)
#pragma unroll
        for (int j = 0; j < 4; j++)
#pragma unroll
            for (int l = 0; l < 4; l++) acc[i][j][l] = 0.0f;

    auto loadA = [&](int c) {
        const float* Ag = A + (size_t)m0 * lda + c * 32;
        float* s = sA + (c & 1) * 128 * PA;
        int col = (tid & 7) * 4;
#pragma unroll
        for (int i = 0; i < 4; i++) {
            int row = i * 32 + (tid >> 3);
            cp16(s + row * PA + col, Ag + (size_t)row * lda + col);
        }
    };
    auto loadB = [&](int c) {
        if (BT) {
            const float* Bg = B + (size_t)n0 * ldb + c * 32;
            float* s = sB + (c & 1) * 128 * PA;
            int col = (tid & 7) * 4;
#pragma unroll
            for (int i = 0; i < 4; i++) {
                int row = i * 32 + (tid >> 3);
                cp16(s + row * PA + col, Bg + (size_t)row * ldb + col);
            }
        } else {
            const float* Bg = B + (size_t)(c * 32) * ldb + n0;
            float* s = sB + (c & 1) * 32 * PBN;
            int col = (tid & 31) * 4;
#pragma unroll
            for (int i = 0; i < 4; i++) {
                int row = i * 8 + (tid >> 5);
                cp16(s + row * PBN + col, Bg + (size_t)row * ldb + col);
            }
        }
    };

    const int nch = K / 32;
    loadA(0); loadB(0); cp_commit();

    for (int c = 0; c < nch; c++) {
        if (c + 1 < nch) {
            loadA(c + 1); loadB(c + 1); cp_commit();
            cp_wait<1>();
        } else {
            cp_wait<0>();
        }
        __syncthreads();

        const float* a = sA + (c & 1) * 128 * PA;
        const float* b = BT ? (sB + (c & 1) * 128 * PA) : (sB + (c & 1) * 32 * PBN);

#pragma unroll
        for (int k8 = 0; k8 < 4; k8++) {
            const int kb = k8 * 8;
            uint32_t af[4][4], bf[4][2];
#pragma unroll
            for (int mt = 0; mt < 4; mt++) {
                int r = wm * 64 + mt * 16;
                af[mt][0] = f2tf32(a[(r + lr)     * PA + kb + lc]);
                af[mt][1] = f2tf32(a[(r + lr + 8) * PA + kb + lc]);
                af[mt][2] = f2tf32(a[(r + lr)     * PA + kb + lc + 4]);
                af[mt][3] = f2tf32(a[(r + lr + 8) * PA + kb + lc + 4]);
            }
#pragma unroll
            for (int nt = 0; nt < 4; nt++) {
                int nn = wn * 32 + nt * 8;
                if (BT) {
                    bf[nt][0] = f2tf32(b[(nn + lr) * PA + kb + lc]);
                    bf[nt][1] = f2tf32(b[(nn + lr) * PA + kb + lc + 4]);
                } else {
                    bf[nt][0] = f2tf32(b[(kb + lc)     * PBN + nn + lr]);
                    bf[nt][1] = f2tf32(b[(kb + lc + 4) * PBN + nn + lr]);
                }
            }
#pragma unroll
            for (int mt = 0; mt < 4; mt++)
#pragma unroll
                for (int nt = 0; nt < 4; nt++)
                    mma_tf32(acc[mt][nt], af[mt], bf[nt]);
        }
        __syncthreads();
    }

    // epilogue
#pragma unroll
    for (int mt = 0; mt < 4; mt++) {
        int r0 = m0 + wm * 64 + mt * 16 + lr;
#pragma unroll
        for (int nt = 0; nt < 4; nt++) {
            int cb = n0 + wn * 32 + nt * 8 + lc * 2;
            float b0 = bias ? bias[cb]     : 0.0f;
            float b1 = bias ? bias[cb + 1] : 0.0f;
            C[(size_t)r0 * ldc + cb]           = acc[mt][nt][0] + b0;
            C[(size_t)r0 * ldc + cb + 1]       = acc[mt][nt][1] + b1;
            C[(size_t)(r0 + 8) * ldc + cb]     = acc[mt][nt][2] + b0;
            C[(size_t)(r0 + 8) * ldc + cb + 1] = acc[mt][nt][3] + b1;
        }
    }
}

#define SMEM_BT ((2*128*PA + 2*128*PA) * 4)   // 73728 B
#define SMEM_NN ((2*128*PA + 2*32*PBN) * 4)   // 71680 B

// ---------------------------------------------------------------------------
// Stage 1: fused QKV projection. N space: [0,2048)->q, [2048,2304)->k, rest->v
// ---------------------------------------------------------------------------
__global__ __launch_bounds__(256, 1)
void qkv_kernel(const float* __restrict__ hs,
                const float* __restrict__ Wq, const float* __restrict__ bq,
                const float* __restrict__ Wk, const float* __restrict__ bk,
                const float* __restrict__ Wv, const float* __restrict__ bv)
{
    int n0 = blockIdx.x * 128;
    int m0 = blockIdx.y * 128;
    const float* W; const float* bias; float* C; int ldc; int nloc;
    if (n0 < 2048)      { W = Wq; bias = bq; C = g_q; ldc = HDIM; nloc = n0; }
    else if (n0 < 2304) { W = Wk; bias = bk; C = g_k; ldc = KDIM; nloc = n0 - 2048; }
    else                { W = Wv; bias = bv; C = g_v; ldc = KDIM; nloc = n0 - 2304; }
    mma_gemm<true>(hs, HID, W, HID, C, ldc, HID, bias, m0, nloc);
}

// ---------------------------------------------------------------------------
// Stage 2: RoPE in place on g_q, g_k.
// ---------------------------------------------------------------------------
__global__ __launch_bounds__(256)
void rope_kernel(const int* __restrict__ pos_ids)
{
    const int QP = BB * SS * HH * HALF;
    const int KP = BB * SS * KHH * HALF;
    int idx = blockIdx.x * 256 + threadIdx.x;
    float* buf; int nh;
    if (idx < QP)           { buf = g_q; nh = HH; }
    else if (idx < QP + KP) { idx -= QP; buf = g_k; nh = KHH; }
    else return;

    int j    = idx & (HALF - 1);
    int rest = idx >> 7;
    int h    = rest % nh; rest /= nh;
    int s    = rest % SS;
    int b    = rest / SS;

    size_t base = (((size_t)b * SS + s) * nh + h) * DD;
    int p = pos_ids[(size_t)b * SS + s];

    double inv_freq = exp(-((double)(2 * j) / (double)DD) * 9.210340371976184);
    float fr = (float)((double)p * inv_freq);
    float sn = sinf(fr), c = cosf(fr);

    float x1 = buf[base + j];
    float x2 = buf[base + HALF + j];
    buf[base + j]        = c * x1 - sn * x2;
    buf[base + HALF + j] = sn * x1 + c * x2;
}

// ---------------------------------------------------------------------------
// Stage 3: scores = Q . K^T per (b,h)
// ---------------------------------------------------------------------------
__global__ __launch_bounds__(256, 1)
void score_kernel(float* __restrict__ attn)
{
    int z = blockIdx.z; int b = z >> 3; int h = z & 7;
    const float* A  = g_q + ((size_t)b * SS * HH + h) * DD;
    const float* Bm = g_k + (size_t)b * SS * KDIM;
    float* C = attn + (size_t)z * SS * SS;
    mma_gemm<true>(A, HDIM, Bm, KDIM, C, SS, DD, nullptr,
                   blockIdx.y * 128, blockIdx.x * 128);
}

// ---------------------------------------------------------------------------
// Stage 4: softmax (scale + mask folded in); one block per row
// ---------------------------------------------------------------------------
__global__ __launch_bounds__(256)
void softmax_kernel(float* __restrict__ attn, const float* __restrict__ mask)
{
    size_t r = blockIdx.x;
    int b = (int)(r / (HH * SS));
    float* row = attn + r * (size_t)SS;
    const float* mrow = mask + (size_t)b * SS;
    int t = threadIdx.x;

    float vals[8];
    float mx = -1e30f;
#pragma unroll
    for (int i = 0; i < 8; i++) {
        float v = row[t + i * 256] * 0.0625f + mrow[t + i * 256];
        vals[i] = v;
        mx = fmaxf(mx, v);
    }
    __shared__ float sred[256];
    sred[t] = mx; __syncthreads();
    for (int s = 128; s > 0; s >>= 1) {
        if (t < s) sred[t] = fmaxf(sred[t], sred[t + s]);
        __syncthreads();
    }
    mx = sred[0]; __syncthreads();

    float sum = 0.0f;
#pragma unroll
    for (int i = 0; i < 8; i++) { vals[i] = expf(vals[i] - mx); sum += vals[i]; }
    sred[t] = sum; __syncthreads();
    for (int s = 128; s > 0; s >>= 1) {
        if (t < s) sred[t] += sred[t + s];
        __syncthreads();
    }
    float inv = 1.0f / sred[0];
#pragma unroll
    for (int i = 0; i < 8; i++) row[t + i * 256] = vals[i] * inv;
}

// ---------------------------------------------------------------------------
// Stage 5: ctx = attn . V   (NN)
// ---------------------------------------------------------------------------
__global__ __launch_bounds__(256, 1)
void av_kernel(const float* __restrict__ attn)
{
    int z = blockIdx.z; int b = z >> 3; int h = z & 7;
    const float* A = attn + (size_t)z * SS * SS;
    const float* V = g_v  + (size_t)b * SS * KDIM;
    float* C = g_ctx + (size_t)b * SS * HDIM + (size_t)h * DD;
    mma_gemm<false>(A, SS, V, KDIM, C, HDIM, SS, nullptr,
                    blockIdx.y * 128, blockIdx.x * 128);
}

// ---------------------------------------------------------------------------
// Stage 6: out = ctx . Wo^T + bo
// ---------------------------------------------------------------------------
__global__ __launch_bounds__(256, 1)
void out_kernel(const float* __restrict__ Wo, const float* __restrict__ bo,
                float* __restrict__ out)
{
    mma_gemm<true>(g_ctx, HDIM, Wo, HDIM, out, HID, HDIM, bo,
                   blockIdx.y * 128, blockIdx.x * 128);
}

// ---------------------------------------------------------------------------
extern "C" void kernel_launch(void* const* d_in, const int* in_sizes, int n_in,
                              void* d_out, int out_size)
{
    const float* hs   = (const float*)d_in[0];
    const float* mask = (const float*)d_in[1];
    const int*   pos  = (const int*)  d_in[2];
    const float* Wq   = (const float*)d_in[3];
    const float* bq   = (const float*)d_in[4];
    const float* Wk   = (const float*)d_in[5];
    const float* bk   = (const float*)d_in[6];
    const float* Wv   = (const float*)d_in[7];
    const float* bv   = (const float*)d_in[8];
    const float* Wo   = (const float*)d_in[9];
    const float* bo   = (const float*)d_in[10];

    float* out = (float*)d_out;
    const size_t OUT_ELEMS  = (size_t)BB * SS * HID;
    const size_t ATTN_ELEMS = (size_t)BB * HH * SS * SS;

    float* attn;
    if ((size_t)out_size >= OUT_ELEMS + ATTN_ELEMS) {
        attn = out + OUT_ELEMS;
    } else {
        cudaGetSymbolAddress((void**)&attn, g_attn_fallback);
    }

    // opt-in to >48KB dynamic smem (persists on the function; cheap host call)
    cudaFuncSetAttribute(qkv_kernel,   cudaFuncAttributeMaxDynamicSharedMemorySize, SMEM_BT);
    cudaFuncSetAttribute(score_kernel, cudaFuncAttributeMaxDynamicSharedMemorySize, SMEM_BT);
    cudaFuncSetAttribute(av_kernel,    cudaFuncAttributeMaxDynamicSharedMemorySize, SMEM_NN);
    cudaFuncSetAttribute(out_kernel,   cudaFuncAttributeMaxDynamicSharedMemorySize, SMEM_BT);

    // 1) QKV projection: N = 2048 + 256 + 256 = 2560
    qkv_kernel<<<dim3(2560 / 128, (BB * SS) / 128), 256, SMEM_BT>>>(hs, Wq, bq, Wk, bk, Wv, bv);

    // 2) RoPE
    {
        int total = BB * SS * HH * HALF + BB * SS * KHH * HALF;
        rope_kernel<<<(total + 255) / 256, 256>>>(pos);
    }

    // 3) scores
    score_kernel<<<dim3(SS / 128, SS / 128, BB * HH), 256, SMEM_BT>>>(attn);

    // 4) softmax
    softmax_kernel<<<BB * HH * SS, 256>>>(attn, mask);

    // 5) ctx = attn . V
    av_kernel<<<dim3(KDIM / 128, SS / 128, BB * HH), 256, SMEM_NN>>>(attn);

    // 6) out projection
    out_kernel<<<dim3(HID / 128, (BB * SS) / 128), 256, SMEM_BT>>>(Wo, bo, out);
}

// round 4
// speedup vs baseline: 5.4315x; 1.7130x over previous
#include <cuda_runtime.h>
#include <cuda_fp16.h>
#include <cstdint>
#include <math.h>

// ---------------------------------------------------------------------------
// Problem constants
// ---------------------------------------------------------------------------
#define BB   2
#define SS   2048
#define HID  2048
#define HH   8
#define KHH  1
#define DD   256
#define HDIM (HH*DD)      // 2048
#define KDIM (KHH*DD)     // 256
#define HALF_D (DD/2)     // 128

// ---------------------------------------------------------------------------
// Scratch (device globals only)
// ---------------------------------------------------------------------------
__device__ __half g_hs16[(size_t)BB*SS*HID];
__device__ __half g_wq16[(size_t)HDIM*HID];
__device__ __half g_wk16[(size_t)KDIM*HID];
__device__ __half g_wv16[(size_t)KDIM*HID];
__device__ __half g_wo16[(size_t)HID*HDIM];
__device__ float  g_qf  [(size_t)BB*SS*HH*DD];
__device__ float  g_kf  [(size_t)BB*SS*KDIM];
__device__ __half g_q16 [(size_t)BB*SS*HH*DD];
__device__ __half g_k16 [(size_t)BB*SS*KDIM];
__device__ __half g_v16 [(size_t)BB*SS*KDIM];
__device__ __half g_vT16[(size_t)BB*KDIM*SS];
__device__ __half g_p16 [(size_t)BB*HH*SS*SS];    // fp16 softmax probs
__device__ __half g_ctx16[(size_t)BB*SS*HDIM];
__device__ float  g_attn_fallback[(size_t)BB*HH*SS*SS];

// ---------------------------------------------------------------------------
// PTX helpers
// ---------------------------------------------------------------------------
__device__ __forceinline__ void cp16s(uint32_t smem_dst, const void* gsrc) {
    asm volatile("cp.async.cg.shared.global [%0], [%1], 16;" :: "r"(smem_dst), "l"(gsrc));
}
__device__ __forceinline__ void cp_commit() { asm volatile("cp.async.commit_group;"); }
template<int N> __device__ __forceinline__ void cp_wait() {
    asm volatile("cp.async.wait_group %0;" :: "n"(N));
}
__device__ __forceinline__ uint32_t smem_u32(const void* p) {
    uint32_t a;
    asm("{ .reg .u64 t; cvta.to.shared.u64 t, %1; cvt.u32.u64 %0, t; }" : "=r"(a) : "l"(p));
    return a;
}
__device__ __forceinline__ void ldm_x4(uint32_t* r, uint32_t addr) {
    asm volatile("ldmatrix.sync.aligned.m8n8.x4.shared.b16 {%0,%1,%2,%3}, [%4];"
        : "=r"(r[0]), "=r"(r[1]), "=r"(r[2]), "=r"(r[3]) : "r"(addr));
}
__device__ __forceinline__ void mma_f16(float* acc, const uint32_t* a, const uint32_t* b) {
    asm volatile("mma.sync.aligned.m16n8k16.row.col.f32.f16.f16.f32 "
        "{%0,%1,%2,%3},{%4,%5,%6,%7},{%8,%9},{%0,%1,%2,%3};"
        : "+f"(acc[0]), "+f"(acc[1]), "+f"(acc[2]), "+f"(acc[3])
        : "r"(a[0]), "r"(a[1]), "r"(a[2]), "r"(a[3]), "r"(b[0]), "r"(b[1]));
}
#define SW128(o) ((o) ^ (((o) >> 3) & 0x70))

// ---------------------------------------------------------------------------
// fp16 tensor-core GEMM: block 128(M) x 128(N), k-chunk 64 halves (128B rows),
// SW128-swizzled smem, cp.async double-buffered, ldmatrix fragments.
//   C = A(M,K) * B(N,K)^T, A/B fp16 k-major, accum fp32, optional bias,
//   C fp32 or fp16 (out16).
// 256 threads = 8 warps (2m x 4n), warp tile 64x32 = 4x4 m16n8k16 grid.
// K must be a multiple of 64 and >= 128 (all call sites: 256 or 2048).
// ---------------------------------------------------------------------------
#define HSMEM_BYTES 65536   // 2 stages x (16KB A + 16KB B)

__device__ void hgemm(const __half* __restrict__ A, int lda,
                      const __half* __restrict__ B, int ldb,
                      void* __restrict__ Cv, int ldc,
                      int K, const float* __restrict__ bias,
                      int m0, int n0, bool out16)
{
    extern __shared__ char smem[];
    const uint32_t sbA = smem_u32(smem);
    const uint32_t sbB = sbA + 32768;
    const int tid = threadIdx.x, lane = tid & 31;
    const int wm = (tid >> 5) >> 2;   // 0..1
    const int wn = (tid >> 5) & 3;    // 0..3

    float acc[4][4][4];
#pragma unroll
    for (int i = 0; i < 4; i++)
#pragma unroll
        for (int j = 0; j < 4; j++)
#pragma unroll
            for (int l = 0; l < 4; l++) acc[i][j][l] = 0.0f;

    auto loadA = [&](int c) {
        uint32_t dst = sbA + (c & 1) * 16384;
        const __half* src = A + (size_t)m0 * lda + c * 64;
#pragma unroll
        for (int i = 0; i < 4; i++) {
            int u = tid + i * 256;          // 0..1023 16B units
            int row = u >> 3, cu = u & 7;
            cp16s(dst + SW128(row * 128 + cu * 16), src + (size_t)row * lda + cu * 8);
        }
    };
    auto loadB = [&](int c) {
        uint32_t dst = sbB + (c & 1) * 16384;
        const __half* src = B + (size_t)n0 * ldb + c * 64;
#pragma unroll
        for (int i = 0; i < 4; i++) {
            int u = tid + i * 256;
            int row = u >> 3, cu = u & 7;
            cp16s(dst + SW128(row * 128 + cu * 16), src + (size_t)row * ldb + cu * 8);
        }
    };

    const int nch = K / 64;
    loadA(0); loadB(0); cp_commit();

    for (int c = 0; c < nch; c++) {
        if (c + 1 < nch) { loadA(c + 1); loadB(c + 1); cp_commit(); cp_wait<1>(); }
        else             { cp_wait<0>(); }
        __syncthreads();

        const uint32_t aB = sbA + (c & 1) * 16384;
        const uint32_t bB = sbB + (c & 1) * 16384;

        // precomputed lane-local offsets
        const int arow_l = lane & 15;
        const int acolh  = (lane >> 4) << 3;                    // +0 / +8 halves
        const int brow_l = (lane & 7) + ((lane >> 4) << 3);     // n within 16
        const int bcolh  = ((lane >> 3) & 1) << 3;

#pragma unroll
        for (int ks = 0; ks < 4; ks++) {
            uint32_t af[4][4], bf[2][4];
#pragma unroll
            for (int mt = 0; mt < 4; mt++) {
                int row = wm * 64 + mt * 16 + arow_l;
                ldm_x4(af[mt], aB + SW128(row * 128 + (ks * 16 + acolh) * 2));
            }
#pragma unroll
            for (int p = 0; p < 2; p++) {
                int row = wn * 32 + p * 16 + brow_l;
                ldm_x4(bf[p], bB + SW128(row * 128 + (ks * 16 + bcolh) * 2));
            }
#pragma unroll
            for (int mt = 0; mt < 4; mt++)
#pragma unroll
                for (int nt = 0; nt < 4; nt++)
                    mma_f16(acc[mt][nt], af[mt], &bf[nt >> 1][(nt & 1) * 2]);
        }
        __syncthreads();
    }

    // epilogue: c frag (c0,c1)->(row=lane/4, col=(lane&3)*2), (c2,c3)->row+8
#pragma unroll
    for (int mt = 0; mt < 4; mt++) {
        int r0 = m0 + wm * 64 + mt * 16 + (lane >> 2);
#pragma unroll
        for (int nt = 0; nt < 4; nt++) {
            int col = n0 + wn * 32 + nt * 8 + (lane & 3) * 2;
            float v0 = acc[mt][nt][0], v1 = acc[mt][nt][1];
            float v2 = acc[mt][nt][2], v3 = acc[mt][nt][3];
            if (bias) {
                float b0 = bias[col], b1 = bias[col + 1];
                v0 += b0; v1 += b1; v2 += b0; v3 += b1;
            }
            if (out16) {
                __half2* C = (__half2*)Cv;
                C[((size_t)r0 * ldc + col) >> 1]       = __floats2half2_rn(v0, v1);
                C[((size_t)(r0 + 8) * ldc + col) >> 1] = __floats2half2_rn(v2, v3);
            } else {
                float* C = (float*)Cv;
                float2 w0 = {v0, v1}, w1 = {v2, v3};
                *(float2*)&C[(size_t)r0 * ldc + col]       = w0;
                *(float2*)&C[(size_t)(r0 + 8) * ldc + col] = w1;
            }
        }
    }
}

// ---------------------------------------------------------------------------
// Stage kernels
// ---------------------------------------------------------------------------
__global__ __launch_bounds__(256)
void qkv_kernel(const float* __restrict__ bq, const float* __restrict__ bk,
                const float* __restrict__ bv)
{
    int bx = blockIdx.x, m0 = blockIdx.y * 128;
    if (bx < 16) {          // Q -> fp32 for rope
        hgemm(g_hs16, HID, g_wq16, HID, g_qf, HDIM, HID, bq, m0, bx * 128, false);
    } else if (bx < 18) {   // K -> fp32 for rope
        hgemm(g_hs16, HID, g_wk16, HID, g_kf, KDIM, HID, bk, m0, (bx - 16) * 128, false);
    } else {                // V -> fp16 directly
        hgemm(g_hs16, HID, g_wv16, HID, g_v16, KDIM, HID, bv, m0, (bx - 18) * 128, true);
    }
}

__global__ __launch_bounds__(256)
void score_kernel(float* __restrict__ attn)
{
    int z = blockIdx.z, b = z >> 3, h = z & 7;
    const __half* A = g_q16 + ((size_t)b * SS * HH + h) * DD;   // row stride HDIM
    const __half* Bm = g_k16 + (size_t)b * SS * KDIM;
    float* C = attn + (size_t)z * SS * SS;
    hgemm(A, HDIM, Bm, KDIM, C, SS, KDIM, nullptr,
          blockIdx.y * 128, blockIdx.x * 128, false);
}

__global__ __launch_bounds__(256)
void av_kernel()
{
    int z = blockIdx.z, b = z >> 3, h = z & 7;
    const __half* A = g_p16 + (size_t)z * SS * SS;
    const __half* Bt = g_vT16 + (size_t)b * KDIM * SS;
    __half* C = g_ctx16 + (size_t)b * SS * HDIM + (size_t)h * DD;
    hgemm(A, SS, Bt, SS, C, HDIM, SS, nullptr,
          blockIdx.y * 128, blockIdx.x * 128, true);
}

__global__ __launch_bounds__(256)
void out_kernel(const float* __restrict__ bo, float* __restrict__ out)
{
    hgemm(g_ctx16, HDIM, g_wo16, HDIM, out, HID, HDIM, bo,
          blockIdx.y * 128, blockIdx.x * 128, false);
}

// ---------------------------------------------------------------------------
// fp32 -> fp16 convert
// ---------------------------------------------------------------------------
__global__ __launch_bounds__(256)
void cvt16_kernel(const float4* __restrict__ src, __half2* __restrict__ dst, int n4)
{
    int i = blockIdx.x * 256 + threadIdx.x;
    if (i < n4) {
        float4 v = src[i];
        dst[2 * i]     = __floats2half2_rn(v.x, v.y);
        dst[2 * i + 1] = __floats2half2_rn(v.z, v.w);
    }
}

// ---------------------------------------------------------------------------
// RoPE: fp32 q/k in -> fp16 q/k out
// ---------------------------------------------------------------------------
__global__ __launch_bounds__(256)
void rope_kernel(const int* __restrict__ pos_ids)
{
    const int QP = BB * SS * HH * HALF_D;
    const int KP = BB * SS * KHH * HALF_D;
    int idx = blockIdx.x * 256 + threadIdx.x;
    const float* src; __half* dst; int nh;
    if (idx < QP)           { src = g_qf; dst = g_q16; nh = HH; }
    else if (idx < QP + KP) { idx -= QP; src = g_kf; dst = g_k16; nh = KHH; }
    else return;

    int j    = idx & (HALF_D - 1);
    int rest = idx >> 7;
    int h    = rest % nh; rest /= nh;
    int s    = rest % SS;
    int b    = rest / SS;

    size_t base = (((size_t)b * SS + s) * nh + h) * DD;
    int p = pos_ids[(size_t)b * SS + s];

    double inv_freq = exp(-((double)(2 * j) / (double)DD) * 9.210340371976184);
    float fr = (float)((double)p * inv_freq);
    float sn = sinf(fr), c = cosf(fr);

    float x1 = src[base + j];
    float x2 = src[base + HALF_D + j];
    dst[base + j]          = __float2half_rn(c * x1 - sn * x2);
    dst[base + HALF_D + j] = __float2half_rn(sn * x1 + c * x2);
}

// ---------------------------------------------------------------------------
// V transpose: g_vT16[b][d][s] = g_v16[b][s][d]   (64x64 tiles)
// ---------------------------------------------------------------------------
__global__ __launch_bounds__(256)
void vt_kernel()
{
    __shared__ __half t[64][72];
    int b  = blockIdx.z;
    int s0 = blockIdx.x * 64, d0 = blockIdx.y * 64;
    int rr = threadIdx.x >> 5;     // 0..7
    int cc = threadIdx.x & 31;     // 0..31
#pragma unroll
    for (int i = 0; i < 8; i++) {
        int s = i * 8 + rr;
        uint32_t v = *(const uint32_t*)&g_v16[((size_t)b * SS + s0 + s) * KDIM + d0 + cc * 2];
        *(uint32_t*)&t[s][cc * 2] = v;
    }
    __syncthreads();
#pragma unroll
    for (int i = 0; i < 8; i++) {
        int d = i * 8 + rr;
        __half2 v = __halves2half2(t[cc * 2][d], t[cc * 2 + 1][d]);
        *(__half2*)&g_vT16[((size_t)b * KDIM + d0 + d) * SS + s0 + cc * 2] = v;
    }
}

// ---------------------------------------------------------------------------
// Softmax: scale+mask folded; fp32 probs (output) + fp16 probs (for AV)
// ---------------------------------------------------------------------------
__global__ __launch_bounds__(256)
void softmax_kernel(float* __restrict__ attn, const float* __restrict__ mask)
{
    size_t r = blockIdx.x;
    int b = (int)(r / (HH * SS));
    float*  row  = attn + r * (size_t)SS;
    __half* prow = g_p16 + r * (size_t)SS;
    const float* mrow = mask + (size_t)b * SS;
    int t = threadIdx.x;

    float vals[8];
    float mx = -1e30f;
#pragma unroll
    for (int i = 0; i < 2; i++) {
        int j = t + i * 256;
        float4 x = ((const float4*)row)[j];
        float4 m = ((const float4*)mrow)[j];
        float* vv = &vals[i * 4];
        vv[0] = x.x * 0.0625f + m.x;  vv[1] = x.y * 0.0625f + m.y;
        vv[2] = x.z * 0.0625f + m.z;  vv[3] = x.w * 0.0625f + m.w;
        mx = fmaxf(mx, fmaxf(fmaxf(vv[0], vv[1]), fmaxf(vv[2], vv[3])));
    }
    __shared__ float sred[256];
    sred[t] = mx; __syncthreads();
    for (int s = 128; s > 0; s >>= 1) {
        if (t < s) sred[t] = fmaxf(sred[t], sred[t + s]);
        __syncthreads();
    }
    mx = sred[0]; __syncthreads();

    float sum = 0.0f;
#pragma unroll
    for (int i = 0; i < 8; i++) { vals[i] = expf(vals[i] - mx); sum += vals[i]; }
    sred[t] = sum; __syncthreads();
    for (int s = 128; s > 0; s >>= 1) {
        if (t < s) sred[t] += sred[t + s];
        __syncthreads();
    }
    float inv = 1.0f / sred[0];
#pragma unroll
    for (int i = 0; i < 2; i++) {
        int j = t + i * 256;
        float4 o;
        o.x = vals[i * 4 + 0] * inv; o.y = vals[i * 4 + 1] * inv;
        o.z = vals[i * 4 + 2] * inv; o.w = vals[i * 4 + 3] * inv;
        ((float4*)row)[j] = o;
        ((__half2*)prow)[2 * j]     = __floats2half2_rn(o.x, o.y);
        ((__half2*)prow)[2 * j + 1] = __floats2half2_rn(o.z, o.w);
    }
}

// ---------------------------------------------------------------------------
extern "C" void kernel_launch(void* const* d_in, const int* in_sizes, int n_in,
                              void* d_out, int out_size)
{
    const float* hs   = (const float*)d_in[0];
    const float* mask = (const float*)d_in[1];
    const int*   pos  = (const int*)  d_in[2];
    const float* Wq   = (const float*)d_in[3];
    const float* bq   = (const float*)d_in[4];
    const float* Wk   = (const float*)d_in[5];
    const float* bk   = (const float*)d_in[6];
    const float* Wv   = (const float*)d_in[7];
    const float* bv   = (const float*)d_in[8];
    const float* Wo   = (const float*)d_in[9];
    const float* bo   = (const float*)d_in[10];

    float* out = (float*)d_out;
    const size_t OUT_ELEMS  = (size_t)BB * SS * HID;
    const size_t ATTN_ELEMS = (size_t)BB * HH * SS * SS;

    float* attn;
    if ((size_t)out_size >= OUT_ELEMS + ATTN_ELEMS) {
        attn = out + OUT_ELEMS;
    } else {
        cudaGetSymbolAddress((void**)&attn, g_attn_fallback);
    }

    __half *p_hs, *p_wq, *p_wk, *p_wv, *p_wo;
    cudaGetSymbolAddress((void**)&p_hs, g_hs16);
    cudaGetSymbolAddress((void**)&p_wq, g_wq16);
    cudaGetSymbolAddress((void**)&p_wk, g_wk16);
    cudaGetSymbolAddress((void**)&p_wv, g_wv16);
    cudaGetSymbolAddress((void**)&p_wo, g_wo16);

    cudaFuncSetAttribute(qkv_kernel,   cudaFuncAttributeMaxDynamicSharedMemorySize, HSMEM_BYTES);
    cudaFuncSetAttribute(score_kernel, cudaFuncAttributeMaxDynamicSharedMemorySize, HSMEM_BYTES);
    cudaFuncSetAttribute(av_kernel,    cudaFuncAttributeMaxDynamicSharedMemorySize, HSMEM_BYTES);
    cudaFuncSetAttribute(out_kernel,   cudaFuncAttributeMaxDynamicSharedMemorySize, HSMEM_BYTES);

    // 0) fp32 -> fp16 operand conversion
    {
        int n;
        n = (BB * SS * HID) / 4; cvt16_kernel<<<(n + 255) / 256, 256>>>((const float4*)hs, (__half2*)p_hs, n);
        n = (HDIM * HID) / 4;    cvt16_kernel<<<(n + 255) / 256, 256>>>((const float4*)Wq, (__half2*)p_wq, n);
        n = (KDIM * HID) / 4;    cvt16_kernel<<<(n + 255) / 256, 256>>>((const float4*)Wk, (__half2*)p_wk, n);
        n = (KDIM * HID) / 4;    cvt16_kernel<<<(n + 255) / 256, 256>>>((const float4*)Wv, (__half2*)p_wv, n);
        n = (HID * HDIM) / 4;    cvt16_kernel<<<(n + 255) / 256, 256>>>((const float4*)Wo, (__half2*)p_wo, n);
    }

    // 1) QKV projection: bx 0-15 q, 16-17 k, 18-19 v
    qkv_kernel<<<dim3(20, (BB * SS) / 128), 256, HSMEM_BYTES>>>(bq, bk, bv);

    // 2) RoPE (fp32 -> fp16)
    {
        int total = BB * SS * HH * HALF_D + BB * SS * KHH * HALF_D;
        rope_kernel<<<(total + 255) / 256, 256>>>(pos);
    }

    // 3) V transpose
    vt_kernel<<<dim3(SS / 64, KDIM / 64, BB), 256>>>();

    // 4) scores = Q.K^T (raw; scale+mask in softmax)
    score_kernel<<<dim3(SS / 128, SS / 128, BB * HH), 256, HSMEM_BYTES>>>(attn);

    // 5) softmax -> fp32 attn (output) + fp16 probs
    softmax_kernel<<<BB * HH * SS, 256>>>(attn, mask);

    // 6) ctx = probs . V
    av_kernel<<<dim3(KDIM / 128, SS / 128, BB * HH), 256, HSMEM_BYTES>>>();

    // 7) out projection
    out_kernel<<<dim3(HID / 128, (BB * SS) / 128), 256, HSMEM_BYTES>>>(bo, out);
}

// round 5
// speedup vs baseline: 5.7715x; 1.0626x over previous
#include <cuda_runtime.h>
#include <cuda_fp16.h>
#include <cstdint>
#include <math.h>

// ---------------------------------------------------------------------------
// Problem constants
// ---------------------------------------------------------------------------
#define BB   2
#define SS   2048
#define HID  2048
#define HH   8
#define KHH  1
#define DD   256
#define HDIM (HH*DD)      // 2048
#define KDIM (KHH*DD)     // 256
#define HALF_D (DD/2)     // 128

// ---------------------------------------------------------------------------
// Scratch (device globals only)
// ---------------------------------------------------------------------------
__device__ __half g_hs16[(size_t)BB*SS*HID];
__device__ __half g_wq16[(size_t)HDIM*HID];
__device__ __half g_wk16[(size_t)KDIM*HID];
__device__ __half g_wv16[(size_t)KDIM*HID];
__device__ __half g_wo16[(size_t)HID*HDIM];
__device__ float  g_qf  [(size_t)BB*SS*HH*DD];
__device__ float  g_kf  [(size_t)BB*SS*KDIM];
__device__ __half g_q16 [(size_t)BB*SS*HH*DD];
__device__ __half g_k16 [(size_t)BB*SS*KDIM];
__device__ __half g_v16 [(size_t)BB*SS*KDIM];
__device__ __half g_vT16[(size_t)BB*KDIM*SS];
__device__ __half g_p16 [(size_t)BB*HH*SS*SS];    // fp16 softmax probs
__device__ __half g_ctx16[(size_t)BB*SS*HDIM];
__device__ float  g_attn_fallback[(size_t)BB*HH*SS*SS];

// ---------------------------------------------------------------------------
// PTX helpers
// ---------------------------------------------------------------------------
__device__ __forceinline__ void cp16s(uint32_t smem_dst, const void* gsrc) {
    asm volatile("cp.async.cg.shared.global [%0], [%1], 16;" :: "r"(smem_dst), "l"(gsrc));
}
__device__ __forceinline__ void cp_commit() { asm volatile("cp.async.commit_group;"); }
template<int N> __device__ __forceinline__ void cp_wait() {
    asm volatile("cp.async.wait_group %0;" :: "n"(N));
}
__device__ __forceinline__ uint32_t smem_u32(const void* p) {
    uint32_t a;
    asm("{ .reg .u64 t; cvta.to.shared.u64 t, %1; cvt.u32.u64 %0, t; }" : "=r"(a) : "l"(p));
    return a;
}
__device__ __forceinline__ void ldm_x4(uint32_t* r, uint32_t addr) {
    asm volatile("ldmatrix.sync.aligned.m8n8.x4.shared.b16 {%0,%1,%2,%3}, [%4];"
        : "=r"(r[0]), "=r"(r[1]), "=r"(r[2]), "=r"(r[3]) : "r"(addr));
}
__device__ __forceinline__ void mma_f16(float* acc, const uint32_t* a, const uint32_t* b) {
    asm volatile("mma.sync.aligned.m16n8k16.row.col.f32.f16.f16.f32 "
        "{%0,%1,%2,%3},{%4,%5,%6,%7},{%8,%9},{%0,%1,%2,%3};"
        : "+f"(acc[0]), "+f"(acc[1]), "+f"(acc[2]), "+f"(acc[3])
        : "r"(a[0]), "r"(a[1]), "r"(a[2]), "r"(a[3]), "r"(b[0]), "r"(b[1]));
}
#define SW128(o) ((o) ^ (((o) >> 3) & 0x70))

// ---------------------------------------------------------------------------
// fp16 tensor-core GEMM: block 128(M) x 256(N), k-chunk 64 halves (128B rows),
// SW128-swizzled smem, 3-stage cp.async pipeline, ldmatrix fragments.
//   C = A(M,K) * B(N,K)^T, fp32 accum, optional bias, C fp32 or fp16.
// 256 threads = 8 warps (2m x 4n), warp tile 64x64 = 4x8 m16n8k16 grid.
// K multiple of 64, >= 192 (call sites: 256 or 2048).
// ---------------------------------------------------------------------------
#define STG_A   16384
#define STG_B   32768
#define HSMEM_BYTES (3 * (STG_A + STG_B))   // 147456

__device__ void hgemm(const __half* __restrict__ A, int lda,
                      const __half* __restrict__ B, int ldb,
                      void* __restrict__ Cv, int ldc,
                      int K, const float* __restrict__ bias,
                      int m0, int n0, bool out16)
{
    extern __shared__ char smem[];
    const uint32_t sbA = smem_u32(smem);            // 3 x 16KB
    const uint32_t sbB = sbA + 3 * STG_A;           // 3 x 32KB
    const int tid = threadIdx.x, lane = tid & 31;
    const int wm = (tid >> 5) >> 2;   // 0..1
    const int wn = (tid >> 5) & 3;    // 0..3

    float acc[4][8][4];
#pragma unroll
    for (int i = 0; i < 4; i++)
#pragma unroll
        for (int j = 0; j < 8; j++)
#pragma unroll
            for (int l = 0; l < 4; l++) acc[i][j][l] = 0.0f;

    auto loadA = [&](int c) {
        uint32_t dst = sbA + (c % 3) * STG_A;
        const __half* src = A + (size_t)m0 * lda + c * 64;
#pragma unroll
        for (int i = 0; i < 4; i++) {
            int u = tid + i * 256;          // 1024 16B units (128 rows x 8)
            int row = u >> 3, cu = u & 7;
            cp16s(dst + SW128(row * 128 + cu * 16), src + (size_t)row * lda + cu * 8);
        }
    };
    auto loadB = [&](int c) {
        uint32_t dst = sbB + (c % 3) * STG_B;
        const __half* src = B + (size_t)n0 * ldb + c * 64;
#pragma unroll
        for (int i = 0; i < 8; i++) {
            int u = tid + i * 256;          // 2048 units (256 rows x 8)
            int row = u >> 3, cu = u & 7;
            cp16s(dst + SW128(row * 128 + cu * 16), src + (size_t)row * ldb + cu * 8);
        }
    };

    const int nch = K / 64;
    loadA(0); loadB(0); cp_commit();
    loadA(1); loadB(1); cp_commit();

    // lane-local ldmatrix offsets
    const int arow_l = lane & 15;
    const int acolh  = (lane >> 4) << 3;
    const int brow_l = (lane & 7) + ((lane >> 4) << 3);
    const int bcolh  = ((lane >> 3) & 1) << 3;

    for (int c = 0; c < nch; c++) {
        if (c + 2 < nch) { loadA(c + 2); loadB(c + 2); cp_commit(); cp_wait<2>(); }
        else if (c + 1 < nch) { cp_wait<1>(); }
        else { cp_wait<0>(); }
        __syncthreads();

        const uint32_t aB = sbA + (c % 3) * STG_A;
        const uint32_t bB = sbB + (c % 3) * STG_B;

#pragma unroll
        for (int ks = 0; ks < 4; ks++) {
            uint32_t af[4][4], bf[4][4];
#pragma unroll
            for (int mt = 0; mt < 4; mt++) {
                int row = wm * 64 + mt * 16 + arow_l;
                ldm_x4(af[mt], aB + SW128(row * 128 + (ks * 16 + acolh) * 2));
            }
#pragma unroll
            for (int p = 0; p < 4; p++) {
                int row = wn * 64 + p * 16 + brow_l;
                ldm_x4(bf[p], bB + SW128(row * 128 + (ks * 16 + bcolh) * 2));
            }
#pragma unroll
            for (int mt = 0; mt < 4; mt++)
#pragma unroll
                for (int nt = 0; nt < 8; nt++)
                    mma_f16(acc[mt][nt], af[mt], &bf[nt >> 1][(nt & 1) * 2]);
        }
        __syncthreads();
    }

    // epilogue
#pragma unroll
    for (int mt = 0; mt < 4; mt++) {
        int r0 = m0 + wm * 64 + mt * 16 + (lane >> 2);
#pragma unroll
        for (int nt = 0; nt < 8; nt++) {
            int col = n0 + wn * 64 + nt * 8 + (lane & 3) * 2;
            float v0 = acc[mt][nt][0], v1 = acc[mt][nt][1];
            float v2 = acc[mt][nt][2], v3 = acc[mt][nt][3];
            if (bias) {
                float b0 = bias[col], b1 = bias[col + 1];
                v0 += b0; v1 += b1; v2 += b0; v3 += b1;
            }
            if (out16) {
                __half2* C = (__half2*)Cv;
                C[((size_t)r0 * ldc + col) >> 1]       = __floats2half2_rn(v0, v1);
                C[((size_t)(r0 + 8) * ldc + col) >> 1] = __floats2half2_rn(v2, v3);
            } else {
                float* C = (float*)Cv;
                float2 w0 = {v0, v1}, w1 = {v2, v3};
                *(float2*)&C[(size_t)r0 * ldc + col]       = w0;
                *(float2*)&C[(size_t)(r0 + 8) * ldc + col] = w1;
            }
        }
    }
}

// ---------------------------------------------------------------------------
// Stage kernels
// ---------------------------------------------------------------------------
__global__ __launch_bounds__(256, 1)
void qkv_kernel(const float* __restrict__ bq, const float* __restrict__ bk,
                const float* __restrict__ bv)
{
    int bx = blockIdx.x, m0 = blockIdx.y * 128;
    if (bx < 8) {           // Q -> fp32 for rope
        hgemm(g_hs16, HID, g_wq16, HID, g_qf, HDIM, HID, bq, m0, bx * 256, false);
    } else if (bx == 8) {   // K -> fp32 for rope
        hgemm(g_hs16, HID, g_wk16, HID, g_kf, KDIM, HID, bk, m0, 0, false);
    } else {                // V -> fp16 directly
        hgemm(g_hs16, HID, g_wv16, HID, g_v16, KDIM, HID, bv, m0, 0, true);
    }
}

__global__ __launch_bounds__(256, 1)
void score_kernel(float* __restrict__ attn)
{
    int z = blockIdx.z, b = z >> 3, h = z & 7;
    const __half* A = g_q16 + ((size_t)b * SS * HH + h) * DD;
    const __half* Bm = g_k16 + (size_t)b * SS * KDIM;
    float* C = attn + (size_t)z * SS * SS;
    hgemm(A, HDIM, Bm, KDIM, C, SS, KDIM, nullptr,
          blockIdx.y * 128, blockIdx.x * 256, false);
}

__global__ __launch_bounds__(256, 1)
void av_kernel()
{
    int z = blockIdx.z, b = z >> 3, h = z & 7;
    const __half* A = g_p16 + (size_t)z * SS * SS;
    const __half* Bt = g_vT16 + (size_t)b * KDIM * SS;
    __half* C = g_ctx16 + (size_t)b * SS * HDIM + (size_t)h * DD;
    hgemm(A, SS, Bt, SS, C, HDIM, SS, nullptr,
          blockIdx.y * 128, 0, true);
}

__global__ __launch_bounds__(256, 1)
void out_kernel(const float* __restrict__ bo, float* __restrict__ out)
{
    hgemm(g_ctx16, HDIM, g_wo16, HDIM, out, HID, HDIM, bo,
          blockIdx.y * 128, blockIdx.x * 256, false);
}

// ---------------------------------------------------------------------------
// fp32 -> fp16 convert
// ---------------------------------------------------------------------------
__global__ __launch_bounds__(256)
void cvt16_kernel(const float4* __restrict__ src, __half2* __restrict__ dst, int n4)
{
    int i = blockIdx.x * 256 + threadIdx.x;
    if (i < n4) {
        float4 v = src[i];
        dst[2 * i]     = __floats2half2_rn(v.x, v.y);
        dst[2 * i + 1] = __floats2half2_rn(v.z, v.w);
    }
}

// ---------------------------------------------------------------------------
// RoPE: fp32 q/k in -> fp16 q/k out
// ---------------------------------------------------------------------------
__global__ __launch_bounds__(256)
void rope_kernel(const int* __restrict__ pos_ids)
{
    const int QP = BB * SS * HH * HALF_D;
    const int KP = BB * SS * KHH * HALF_D;
    int idx = blockIdx.x * 256 + threadIdx.x;
    const float* src; __half* dst; int nh;
    if (idx < QP)           { src = g_qf; dst = g_q16; nh = HH; }
    else if (idx < QP + KP) { idx -= QP; src = g_kf; dst = g_k16; nh = KHH; }
    else return;

    int j    = idx & (HALF_D - 1);
    int rest = idx >> 7;
    int h    = rest % nh; rest /= nh;
    int s    = rest % SS;
    int b    = rest / SS;

    size_t base = (((size_t)b * SS + s) * nh + h) * DD;
    int p = pos_ids[(size_t)b * SS + s];

    double inv_freq = exp(-((double)(2 * j) / (double)DD) * 9.210340371976184);
    float fr = (float)((double)p * inv_freq);
    float sn = sinf(fr), c = cosf(fr);

    float x1 = src[base + j];
    float x2 = src[base + HALF_D + j];
    dst[base + j]          = __float2half_rn(c * x1 - sn * x2);
    dst[base + HALF_D + j] = __float2half_rn(sn * x1 + c * x2);
}

// ---------------------------------------------------------------------------
// V transpose: g_vT16[b][d][s] = g_v16[b][s][d]   (64x64 tiles)
// ---------------------------------------------------------------------------
__global__ __launch_bounds__(256)
void vt_kernel()
{
    __shared__ __half t[64][72];
    int b  = blockIdx.z;
    int s0 = blockIdx.x * 64, d0 = blockIdx.y * 64;
    int rr = threadIdx.x >> 5;
    int cc = threadIdx.x & 31;
#pragma unroll
    for (int i = 0; i < 8; i++) {
        int s = i * 8 + rr;
        uint32_t v = *(const uint32_t*)&g_v16[((size_t)b * SS + s0 + s) * KDIM + d0 + cc * 2];
        *(uint32_t*)&t[s][cc * 2] = v;
    }
    __syncthreads();
#pragma unroll
    for (int i = 0; i < 8; i++) {
        int d = i * 8 + rr;
        __half2 v = __halves2half2(t[cc * 2][d], t[cc * 2 + 1][d]);
        *(__half2*)&g_vT16[((size_t)b * KDIM + d0 + d) * SS + s0 + cc * 2] = v;
    }
}

// ---------------------------------------------------------------------------
// Softmax: scale+mask folded; fp32 probs (output) + fp16 probs (for AV).
// Warp-shuffle reductions, 2 syncthreads total.
// ---------------------------------------------------------------------------
__global__ __launch_bounds__(256)
void softmax_kernel(float* __restrict__ attn, const float* __restrict__ mask)
{
    size_t r = blockIdx.x;
    int b = (int)(r / (HH * SS));
    float*  row  = attn + r * (size_t)SS;
    __half* prow = g_p16 + r * (size_t)SS;
    const float* mrow = mask + (size_t)b * SS;
    int t = threadIdx.x, lane = t & 31, w = t >> 5;

    float vals[8];
    float mx = -1e30f;
#pragma unroll
    for (int i = 0; i < 2; i++) {
        int j = t + i * 256;
        float4 x = ((const float4*)row)[j];
        float4 m = ((const float4*)mrow)[j];
        float* vv = &vals[i * 4];
        vv[0] = x.x * 0.0625f + m.x;  vv[1] = x.y * 0.0625f + m.y;
        vv[2] = x.z * 0.0625f + m.z;  vv[3] = x.w * 0.0625f + m.w;
        mx = fmaxf(mx, fmaxf(fmaxf(vv[0], vv[1]), fmaxf(vv[2], vv[3])));
    }
#pragma unroll
    for (int o = 16; o > 0; o >>= 1) mx = fmaxf(mx, __shfl_xor_sync(~0u, mx, o));
    __shared__ float smx[8], ssm[8];
    if (lane == 0) smx[w] = mx;
    __syncthreads();
    float M = smx[0];
#pragma unroll
    for (int k = 1; k < 8; k++) M = fmaxf(M, smx[k]);

    float sum = 0.0f;
#pragma unroll
    for (int i = 0; i < 8; i++) { vals[i] = __expf(vals[i] - M); sum += vals[i]; }
#pragma unroll
    for (int o = 16; o > 0; o >>= 1) sum += __shfl_xor_sync(~0u, sum, o);
    if (lane == 0) ssm[w] = sum;
    __syncthreads();
    float tot = ssm[0];
#pragma unroll
    for (int k = 1; k < 8; k++) tot += ssm[k];
    float inv = 1.0f / tot;

#pragma unroll
    for (int i = 0; i < 2; i++) {
        int j = t + i * 256;
        float4 o;
        o.x = vals[i * 4 + 0] * inv; o.y = vals[i * 4 + 1] * inv;
        o.z = vals[i * 4 + 2] * inv; o.w = vals[i * 4 + 3] * inv;
        ((float4*)row)[j] = o;
        ((__half2*)prow)[2 * j]     = __floats2half2_rn(o.x, o.y);
        ((__half2*)prow)[2 * j + 1] = __floats2half2_rn(o.z, o.w);
    }
}

// ---------------------------------------------------------------------------
extern "C" void kernel_launch(void* const* d_in, const int* in_sizes, int n_in,
                              void* d_out, int out_size)
{
    const float* hs   = (const float*)d_in[0];
    const float* mask = (const float*)d_in[1];
    const int*   pos  = (const int*)  d_in[2];
    const float* Wq   = (const float*)d_in[3];
    const float* bq   = (const float*)d_in[4];
    const float* Wk   = (const float*)d_in[5];
    const float* bk   = (const float*)d_in[6];
    const float* Wv   = (const float*)d_in[7];
    const float* bv   = (const float*)d_in[8];
    const float* Wo   = (const float*)d_in[9];
    const float* bo   = (const float*)d_in[10];

    float* out = (float*)d_out;
    const size_t OUT_ELEMS  = (size_t)BB * SS * HID;
    const size_t ATTN_ELEMS = (size_t)BB * HH * SS * SS;

    float* attn;
    if ((size_t)out_size >= OUT_ELEMS + ATTN_ELEMS) {
        attn = out + OUT_ELEMS;
    } else {
        cudaGetSymbolAddress((void**)&attn, g_attn_fallback);
    }

    __half *p_hs, *p_wq, *p_wk, *p_wv, *p_wo;
    cudaGetSymbolAddress((void**)&p_hs, g_hs16);
    cudaGetSymbolAddress((void**)&p_wq, g_wq16);
    cudaGetSymbolAddress((void**)&p_wk, g_wk16);
    cudaGetSymbolAddress((void**)&p_wv, g_wv16);
    cudaGetSymbolAddress((void**)&p_wo, g_wo16);

    cudaFuncSetAttribute(qkv_kernel,   cudaFuncAttributeMaxDynamicSharedMemorySize, HSMEM_BYTES);
    cudaFuncSetAttribute(score_kernel, cudaFuncAttributeMaxDynamicSharedMemorySize, HSMEM_BYTES);
    cudaFuncSetAttribute(av_kernel,    cudaFuncAttributeMaxDynamicSharedMemorySize, HSMEM_BYTES);
    cudaFuncSetAttribute(out_kernel,   cudaFuncAttributeMaxDynamicSharedMemorySize, HSMEM_BYTES);

    // 0) fp32 -> fp16 operand conversion
    {
        int n;
        n = (BB * SS * HID) / 4; cvt16_kernel<<<(n + 255) / 256, 256>>>((const float4*)hs, (__half2*)p_hs, n);
        n = (HDIM * HID) / 4;    cvt16_kernel<<<(n + 255) / 256, 256>>>((const float4*)Wq, (__half2*)p_wq, n);
        n = (KDIM * HID) / 4;    cvt16_kernel<<<(n + 255) / 256, 256>>>((const float4*)Wk, (__half2*)p_wk, n);
        n = (KDIM * HID) / 4;    cvt16_kernel<<<(n + 255) / 256, 256>>>((const float4*)Wv, (__half2*)p_wv, n);
        n = (HID * HDIM) / 4;    cvt16_kernel<<<(n + 255) / 256, 256>>>((const float4*)Wo, (__half2*)p_wo, n);
    }

    // 1) QKV projection: bx 0-7 q (N=2048), 8 k, 9 v
    qkv_kernel<<<dim3(10, (BB * SS) / 128), 256, HSMEM_BYTES>>>(bq, bk, bv);

    // 2) RoPE (fp32 -> fp16)
    {
        int total = BB * SS * HH * HALF_D + BB * SS * KHH * HALF_D;
        rope_kernel<<<(total + 255) / 256, 256>>>(pos);
    }

    // 3) V transpose
    vt_kernel<<<dim3(SS / 64, KDIM / 64, BB), 256>>>();

    // 4) scores = Q.K^T (raw; scale+mask in softmax)
    score_kernel<<<dim3(SS / 256, SS / 128, BB * HH), 256, HSMEM_BYTES>>>(attn);

    // 5) softmax -> fp32 attn (output) + fp16 probs
    softmax_kernel<<<BB * HH * SS, 256>>>(attn, mask);

    // 6) ctx = probs . V
    av_kernel<<<dim3(KDIM / 256, SS / 128, BB * HH), 256, HSMEM_BYTES>>>();

    // 7) out projection
    out_kernel<<<dim3(HID / 256, (BB * SS) / 128), 256, HSMEM_BYTES>>>(bo, out);
}

// round 6
// speedup vs baseline: 6.2883x; 1.0895x over previous
#include <cuda_runtime.h>
#include <cuda_fp16.h>
#include <cstdint>
#include <math.h>

// ---------------------------------------------------------------------------
// Problem constants
// ---------------------------------------------------------------------------
#define BB   2
#define SS   2048
#define HID  2048
#define HH   8
#define KHH  1
#define DD   256
#define HDIM (HH*DD)      // 2048
#define KDIM (KHH*DD)     // 256
#define HALF_D (DD/2)     // 128
#define MSCALE 0.0625f    // D^-0.5
#define ESHIFT 2.0f       // exp shift (cancels in normalization; bounds fp16 e)

// ---------------------------------------------------------------------------
// Scratch (device globals only)
// ---------------------------------------------------------------------------
__device__ __half g_hs16[(size_t)BB*SS*HID];
__device__ __half g_wq16[(size_t)HDIM*HID];
__device__ __half g_wk16[(size_t)KDIM*HID];
__device__ __half g_wv16[(size_t)KDIM*HID];
__device__ __half g_wo16[(size_t)HID*HDIM];
__device__ float  g_qf  [(size_t)BB*SS*HH*DD];
__device__ float  g_kf  [(size_t)BB*SS*KDIM];
__device__ __half g_q16 [(size_t)BB*SS*HH*DD];
__device__ __half g_k16 [(size_t)BB*SS*KDIM];
__device__ __half g_v16 [(size_t)BB*SS*KDIM];
__device__ __half g_vT16[(size_t)BB*KDIM*SS];
__device__ __half g_p16 [(size_t)BB*HH*SS*SS];    // UNNORMALIZED exp(score) fp16
__device__ float  g_rowsum[(size_t)BB*HH*SS];     // per attn-row sum of e
__device__ __half g_ctx16[(size_t)BB*SS*HDIM];
__device__ float  g_attn_fallback[(size_t)BB*HH*SS*SS];

// ---------------------------------------------------------------------------
// PTX helpers
// ---------------------------------------------------------------------------
__device__ __forceinline__ void cp16s(uint32_t smem_dst, const void* gsrc) {
    asm volatile("cp.async.cg.shared.global [%0], [%1], 16;" :: "r"(smem_dst), "l"(gsrc));
}
__device__ __forceinline__ void cp_commit() { asm volatile("cp.async.commit_group;"); }
template<int N> __device__ __forceinline__ void cp_wait() {
    asm volatile("cp.async.wait_group %0;" :: "n"(N));
}
__device__ __forceinline__ uint32_t smem_u32(const void* p) {
    uint32_t a;
    asm("{ .reg .u64 t; cvta.to.shared.u64 t, %1; cvt.u32.u64 %0, t; }" : "=r"(a) : "l"(p));
    return a;
}
__device__ __forceinline__ void ldm_x4(uint32_t* r, uint32_t addr) {
    asm volatile("ldmatrix.sync.aligned.m8n8.x4.shared.b16 {%0,%1,%2,%3}, [%4];"
        : "=r"(r[0]), "=r"(r[1]), "=r"(r[2]), "=r"(r[3]) : "r"(addr));
}
__device__ __forceinline__ void mma_f16(float* acc, const uint32_t* a, const uint32_t* b) {
    asm volatile("mma.sync.aligned.m16n8k16.row.col.f32.f16.f16.f32 "
        "{%0,%1,%2,%3},{%4,%5,%6,%7},{%8,%9},{%0,%1,%2,%3};"
        : "+f"(acc[0]), "+f"(acc[1]), "+f"(acc[2]), "+f"(acc[3])
        : "r"(a[0]), "r"(a[1]), "r"(a[2]), "r"(a[3]), "r"(b[0]), "r"(b[1]));
}
#define SW128(o) ((o) ^ (((o) >> 3) & 0x70))

// ---------------------------------------------------------------------------
// fp16 tensor-core GEMM: block 128x128, k-chunk 64 halves, SW128 swizzle,
// 3-stage cp.async pipeline, 128 threads = 4 warps (2m x 2n), warp 64x64.
// 2 CTAs/SM.  C = A(M,K) * B(N,K)^T, fp32 accum.
// MODE 0: fp32 out (+bias)     MODE 1: fp16 out (+bias)
// MODE 2: e = expf(acc*MSCALE + mask[col] - ESHIFT) -> fp16 out + atomic rowsum
// MODE 3: fp16 out scaled by 1/rsum[row]
// ---------------------------------------------------------------------------
#define STG     16384
#define HSMEM_BYTES (6 * STG)    // 98304

template<int MODE>
__device__ __forceinline__ void hgemm(
    const __half* __restrict__ A, int lda,
    const __half* __restrict__ B, int ldb,
    void* __restrict__ Cv, int ldc,
    int K, const float* __restrict__ bias,
    const float* __restrict__ maskrow, float* __restrict__ rsum,
    int m0, int n0)
{
    extern __shared__ char smem[];
    const uint32_t sbA = smem_u32(smem);        // 3 x 16KB
    const uint32_t sbB = sbA + 3 * STG;         // 3 x 16KB
    const int tid = threadIdx.x, lane = tid & 31;
    const int wm = (tid >> 5) >> 1;   // 0..1
    const int wn = (tid >> 5) & 1;    // 0..1

    float acc[4][8][4];
#pragma unroll
    for (int i = 0; i < 4; i++)
#pragma unroll
        for (int j = 0; j < 8; j++)
#pragma unroll
            for (int l = 0; l < 4; l++) acc[i][j][l] = 0.0f;

    auto loadA = [&](int c) {
        uint32_t dst = sbA + (c % 3) * STG;
        const __half* src = A + (size_t)m0 * lda + c * 64;
#pragma unroll
        for (int i = 0; i < 8; i++) {
            int u = tid + i * 128;          // 1024 16B units (128 rows x 8)
            int row = u >> 3, cu = u & 7;
            cp16s(dst + SW128(row * 128 + cu * 16), src + (size_t)row * lda + cu * 8);
        }
    };
    auto loadB = [&](int c) {
        uint32_t dst = sbB + (c % 3) * STG;
        const __half* src = B + (size_t)n0 * ldb + c * 64;
#pragma unroll
        for (int i = 0; i < 8; i++) {
            int u = tid + i * 128;
            int row = u >> 3, cu = u & 7;
            cp16s(dst + SW128(row * 128 + cu * 16), src + (size_t)row * ldb + cu * 8);
        }
    };

    const int nch = K / 64;
    loadA(0); loadB(0); cp_commit();
    loadA(1); loadB(1); cp_commit();

    const int arow_l = lane & 15;
    const int acolh  = (lane >> 4) << 3;
    const int brow_l = (lane & 7) + ((lane >> 4) << 3);
    const int bcolh  = ((lane >> 3) & 1) << 3;

    for (int c = 0; c < nch; c++) {
        if (c + 2 < nch) { loadA(c + 2); loadB(c + 2); cp_commit(); cp_wait<2>(); }
        else if (c + 1 < nch) { cp_wait<1>(); }
        else { cp_wait<0>(); }
        __syncthreads();

        const uint32_t aB = sbA + (c % 3) * STG;
        const uint32_t bB = sbB + (c % 3) * STG;

#pragma unroll
        for (int ks = 0; ks < 4; ks++) {
            uint32_t af[4][4], bf[4][4];
#pragma unroll
            for (int mt = 0; mt < 4; mt++) {
                int row = wm * 64 + mt * 16 + arow_l;
                ldm_x4(af[mt], aB + SW128(row * 128 + (ks * 16 + acolh) * 2));
            }
#pragma unroll
            for (int p = 0; p < 4; p++) {
                int row = wn * 64 + p * 16 + brow_l;
                ldm_x4(bf[p], bB + SW128(row * 128 + (ks * 16 + bcolh) * 2));
            }
#pragma unroll
            for (int mt = 0; mt < 4; mt++)
#pragma unroll
                for (int nt = 0; nt < 8; nt++)
                    mma_f16(acc[mt][nt], af[mt], &bf[nt >> 1][(nt & 1) * 2]);
        }
        __syncthreads();
    }

    // ---- epilogue ----
#pragma unroll
    for (int mt = 0; mt < 4; mt++) {
        int r0 = m0 + wm * 64 + mt * 16 + (lane >> 2);    // global row
        if (MODE == 2) {
            float pA = 0.0f, pB = 0.0f;
            __half* C = (__half*)Cv;
#pragma unroll
            for (int nt = 0; nt < 8; nt++) {
                int col = n0 + wn * 64 + nt * 8 + (lane & 3) * 2;
                float mk0 = maskrow[col], mk1 = maskrow[col + 1];
                float e0 = __expf(acc[mt][nt][0] * MSCALE + mk0 - ESHIFT);
                float e1 = __expf(acc[mt][nt][1] * MSCALE + mk1 - ESHIFT);
                float e2 = __expf(acc[mt][nt][2] * MSCALE + mk0 - ESHIFT);
                float e3 = __expf(acc[mt][nt][3] * MSCALE + mk1 - ESHIFT);
                *(__half2*)&C[(size_t)r0 * ldc + col]       = __floats2half2_rn(e0, e1);
                *(__half2*)&C[(size_t)(r0 + 8) * ldc + col] = __floats2half2_rn(e2, e3);
                pA += e0 + e1;
                pB += e2 + e3;
            }
            // reduce across the 4 lanes sharing each row (lanes r*4 .. r*4+3)
            pA += __shfl_xor_sync(~0u, pA, 1); pA += __shfl_xor_sync(~0u, pA, 2);
            pB += __shfl_xor_sync(~0u, pB, 1); pB += __shfl_xor_sync(~0u, pB, 2);
            if ((lane & 3) == 0) {
                atomicAdd(&rsum[r0], pA);
                atomicAdd(&rsum[r0 + 8], pB);
            }
        } else if (MODE == 3) {
            float ia = 1.0f / rsum[r0];
            float ib = 1.0f / rsum[r0 + 8];
            __half2* C = (__half2*)Cv;
#pragma unroll
            for (int nt = 0; nt < 8; nt++) {
                int col = n0 + wn * 64 + nt * 8 + (lane & 3) * 2;
                C[((size_t)r0 * ldc + col) >> 1]       = __floats2half2_rn(acc[mt][nt][0] * ia, acc[mt][nt][1] * ia);
                C[((size_t)(r0 + 8) * ldc + col) >> 1] = __floats2half2_rn(acc[mt][nt][2] * ib, acc[mt][nt][3] * ib);
            }
        } else {
#pragma unroll
            for (int nt = 0; nt < 8; nt++) {
                int col = n0 + wn * 64 + nt * 8 + (lane & 3) * 2;
                float v0 = acc[mt][nt][0], v1 = acc[mt][nt][1];
                float v2 = acc[mt][nt][2], v3 = acc[mt][nt][3];
                if (bias) {
                    float b0 = bias[col], b1 = bias[col + 1];
                    v0 += b0; v1 += b1; v2 += b0; v3 += b1;
                }
                if (MODE == 1) {
                    __half2* C = (__half2*)Cv;
                    C[((size_t)r0 * ldc + col) >> 1]       = __floats2half2_rn(v0, v1);
                    C[((size_t)(r0 + 8) * ldc + col) >> 1] = __floats2half2_rn(v2, v3);
                } else {
                    float* C = (float*)Cv;
                    float2 w0 = {v0, v1}, w1 = {v2, v3};
                    *(float2*)&C[(size_t)r0 * ldc + col]       = w0;
                    *(float2*)&C[(size_t)(r0 + 8) * ldc + col] = w1;
                }
            }
        }
    }
}

// ---------------------------------------------------------------------------
// Stage kernels (128 threads, 2 CTAs/SM)
// ---------------------------------------------------------------------------
__global__ __launch_bounds__(128, 2)
void qkv_kernel(const float* __restrict__ bq, const float* __restrict__ bk,
                const float* __restrict__ bv)
{
    int bx = blockIdx.x, m0 = blockIdx.y * 128;
    if (bx < 16) {          // Q -> fp32 for rope
        hgemm<0>(g_hs16, HID, g_wq16, HID, g_qf, HDIM, HID, bq, nullptr, nullptr, m0, bx * 128);
    } else if (bx < 18) {   // K -> fp32 for rope
        hgemm<0>(g_hs16, HID, g_wk16, HID, g_kf, KDIM, HID, bk, nullptr, nullptr, m0, (bx - 16) * 128);
    } else {                // V -> fp16 directly
        hgemm<1>(g_hs16, HID, g_wv16, HID, g_v16, KDIM, HID, bv, nullptr, nullptr, m0, (bx - 18) * 128);
    }
}

__global__ __launch_bounds__(128, 2)
void score_kernel(const float* __restrict__ mask)
{
    int z = blockIdx.z, b = z >> 3, h = z & 7;
    const __half* A  = g_q16 + ((size_t)b * SS * HH + h) * DD;
    const __half* Bm = g_k16 + (size_t)b * SS * KDIM;
    __half* C = g_p16 + (size_t)z * SS * SS;
    hgemm<2>(A, HDIM, Bm, KDIM, C, SS, KDIM, nullptr,
             mask + (size_t)b * SS, g_rowsum + (size_t)z * SS,
             blockIdx.y * 128, blockIdx.x * 128);
}

__global__ __launch_bounds__(128, 2)
void av_kernel()
{
    int z = blockIdx.z, b = z >> 3, h = z & 7;
    const __half* A  = g_p16 + (size_t)z * SS * SS;
    const __half* Bt = g_vT16 + (size_t)b * KDIM * SS;
    __half* C = g_ctx16 + (size_t)b * SS * HDIM + (size_t)h * DD;
    hgemm<3>(A, SS, Bt, SS, C, HDIM, SS, nullptr, nullptr,
             g_rowsum + (size_t)z * SS, blockIdx.y * 128, blockIdx.x * 128);
}

__global__ __launch_bounds__(128, 2)
void out_kernel(const float* __restrict__ bo, float* __restrict__ out)
{
    hgemm<0>(g_ctx16, HDIM, g_wo16, HDIM, out, HID, HDIM, bo, nullptr, nullptr,
             blockIdx.y * 128, blockIdx.x * 128);
}

// ---------------------------------------------------------------------------
// small kernels
// ---------------------------------------------------------------------------
__global__ __launch_bounds__(256)
void zero_rowsum_kernel()
{
    g_rowsum[blockIdx.x * 256 + threadIdx.x] = 0.0f;
}

// attn[idx] = (float)e16[idx] / rowsum[row]   (8 elems/thread, same row)
__global__ __launch_bounds__(256)
void normalize_kernel(float* __restrict__ attn)
{
    size_t base = ((size_t)blockIdx.x * 256 + threadIdx.x) * 8;
    float inv = 1.0f / g_rowsum[base >> 11];
    const __half2* src = (const __half2*)&g_p16[base];
    float4* dst = (float4*)&attn[base];
    float4 o0, o1;
    float2 a = __half22float2(src[0]), b = __half22float2(src[1]);
    float2 c = __half22float2(src[2]), d = __half22float2(src[3]);
    o0.x = a.x * inv; o0.y = a.y * inv; o0.z = b.x * inv; o0.w = b.y * inv;
    o1.x = c.x * inv; o1.y = c.y * inv; o1.z = d.x * inv; o1.w = d.y * inv;
    dst[0] = o0; dst[1] = o1;
}

__global__ __launch_bounds__(256)
void cvt16_kernel(const float4* __restrict__ src, __half2* __restrict__ dst, int n4)
{
    int i = blockIdx.x * 256 + threadIdx.x;
    if (i < n4) {
        float4 v = src[i];
        dst[2 * i]     = __floats2half2_rn(v.x, v.y);
        dst[2 * i + 1] = __floats2half2_rn(v.z, v.w);
    }
}

__global__ __launch_bounds__(256)
void rope_kernel(const int* __restrict__ pos_ids)
{
    const int QP = BB * SS * HH * HALF_D;
    const int KP = BB * SS * KHH * HALF_D;
    int idx = blockIdx.x * 256 + threadIdx.x;
    const float* src; __half* dst; int nh;
    if (idx < QP)           { src = g_qf; dst = g_q16; nh = HH; }
    else if (idx < QP + KP) { idx -= QP; src = g_kf; dst = g_k16; nh = KHH; }
    else return;

    int j    = idx & (HALF_D - 1);
    int rest = idx >> 7;
    int h    = rest % nh; rest /= nh;
    int s    = rest % SS;
    int b    = rest / SS;

    size_t base = (((size_t)b * SS + s) * nh + h) * DD;
    int p = pos_ids[(size_t)b * SS + s];

    double inv_freq = exp(-((double)(2 * j) / (double)DD) * 9.210340371976184);
    float fr = (float)((double)p * inv_freq);
    float sn = sinf(fr), c = cosf(fr);

    float x1 = src[base + j];
    float x2 = src[base + HALF_D + j];
    dst[base + j]          = __float2half_rn(c * x1 - sn * x2);
    dst[base + HALF_D + j] = __float2half_rn(sn * x1 + c * x2);
}

__global__ __launch_bounds__(256)
void vt_kernel()
{
    __shared__ __half t[64][72];
    int b  = blockIdx.z;
    int s0 = blockIdx.x * 64, d0 = blockIdx.y * 64;
    int rr = threadIdx.x >> 5;
    int cc = threadIdx.x & 31;
#pragma unroll
    for (int i = 0; i < 8; i++) {
        int s = i * 8 + rr;
        uint32_t v = *(const uint32_t*)&g_v16[((size_t)b * SS + s0 + s) * KDIM + d0 + cc * 2];
        *(uint32_t*)&t[s][cc * 2] = v;
    }
    __syncthreads();
#pragma unroll
    for (int i = 0; i < 8; i++) {
        int d = i * 8 + rr;
        __half2 v = __halves2half2(t[cc * 2][d], t[cc * 2 + 1][d]);
        *(__half2*)&g_vT16[((size_t)b * KDIM + d0 + d) * SS + s0 + cc * 2] = v;
    }
}

// ---------------------------------------------------------------------------
extern "C" void kernel_launch(void* const* d_in, const int* in_sizes, int n_in,
                              void* d_out, int out_size)
{
    const float* hs   = (const float*)d_in[0];
    const float* mask = (const float*)d_in[1];
    const int*   pos  = (const int*)  d_in[2];
    const float* Wq   = (const float*)d_in[3];
    const float* bq   = (const float*)d_in[4];
    const float* Wk   = (const float*)d_in[5];
    const float* bk   = (const float*)d_in[6];
    const float* Wv   = (const float*)d_in[7];
    const float* bv   = (const float*)d_in[8];
    const float* Wo   = (const float*)d_in[9];
    const float* bo   = (const float*)d_in[10];

    float* out = (float*)d_out;
    const size_t OUT_ELEMS  = (size_t)BB * SS * HID;
    const size_t ATTN_ELEMS = (size_t)BB * HH * SS * SS;

    float* attn;
    if ((size_t)out_size >= OUT_ELEMS + ATTN_ELEMS) {
        attn = out + OUT_ELEMS;
    } else {
        cudaGetSymbolAddress((void**)&attn, g_attn_fallback);
    }

    __half *p_hs, *p_wq, *p_wk, *p_wv, *p_wo;
    cudaGetSymbolAddress((void**)&p_hs, g_hs16);
    cudaGetSymbolAddress((void**)&p_wq, g_wq16);
    cudaGetSymbolAddress((void**)&p_wk, g_wk16);
    cudaGetSymbolAddress((void**)&p_wv, g_wv16);
    cudaGetSymbolAddress((void**)&p_wo, g_wo16);

    cudaFuncSetAttribute(qkv_kernel,   cudaFuncAttributeMaxDynamicSharedMemorySize, HSMEM_BYTES);
    cudaFuncSetAttribute(score_kernel, cudaFuncAttributeMaxDynamicSharedMemorySize, HSMEM_BYTES);
    cudaFuncSetAttribute(av_kernel,    cudaFuncAttributeMaxDynamicSharedMemorySize, HSMEM_BYTES);
    cudaFuncSetAttribute(out_kernel,   cudaFuncAttributeMaxDynamicSharedMemorySize, HSMEM_BYTES);

    // 0) fp32 -> fp16 operand conversion
    {
        int n;
        n = (BB * SS * HID) / 4; cvt16_kernel<<<(n + 255) / 256, 256>>>((const float4*)hs, (__half2*)p_hs, n);
        n = (HDIM * HID) / 4;    cvt16_kernel<<<(n + 255) / 256, 256>>>((const float4*)Wq, (__half2*)p_wq, n);
        n = (KDIM * HID) / 4;    cvt16_kernel<<<(n + 255) / 256, 256>>>((const float4*)Wk, (__half2*)p_wk, n);
        n = (KDIM * HID) / 4;    cvt16_kernel<<<(n + 255) / 256, 256>>>((const float4*)Wv, (__half2*)p_wv, n);
        n = (HID * HDIM) / 4;    cvt16_kernel<<<(n + 255) / 256, 256>>>((const float4*)Wo, (__half2*)p_wo, n);
    }

    // 1) QKV projection: bx 0-15 q, 16-17 k, 18-19 v
    qkv_kernel<<<dim3(20, (BB * SS) / 128), 128, HSMEM_BYTES>>>(bq, bk, bv);

    // 2) RoPE (fp32 -> fp16)
    {
        int total = BB * SS * HH * HALF_D + BB * SS * KHH * HALF_D;
        rope_kernel<<<(total + 255) / 256, 256>>>(pos);
    }

    // 3) V transpose
    vt_kernel<<<dim3(SS / 64, KDIM / 64, BB), 256>>>();

    // 4) zero row sums, then scores with fused exp (writes e16 + rowsum)
    zero_rowsum_kernel<<<(BB * HH * SS) / 256, 256>>>();
    score_kernel<<<dim3(SS / 128, SS / 128, BB * HH), 128, HSMEM_BYTES>>>(mask);

    // 5) ctx = (e . V) / rowsum
    av_kernel<<<dim3(KDIM / 128, SS / 128, BB * HH), 128, HSMEM_BYTES>>>();

    // 6) out projection
    out_kernel<<<dim3(HID / 128, (BB * SS) / 128), 128, HSMEM_BYTES>>>(bo, out);

    // 7) attn output = e16 / rowsum
    normalize_kernel<<<(int)(ATTN_ELEMS / (256 * 8)), 256>>>(attn);
}